// round 3
// baseline (speedup 1.0000x reference)
#include <cuda_runtime.h>
#include <math.h>

// ---------------- problem constants ----------------
#define NN   10000
#define TT   6
#define HIDD 64
#define EE   160000
#define EP   170000          // EE + NN self loops
#define ROWS (TT*NN)         // 60000

// ---------------- scratch (__device__ globals; no allocations) ----------------
__device__ float  g_XT  [ROWS*64];
__device__ float  g_XW0 [ROWS*64];
__device__ float  g_H0  [ROWS*64];
__device__ float  g_XW1 [ROWS*256];
__device__ float  g_HS  [ROWS*64];
__device__ float  g_GI  [ROWS*192];
__device__ float  g_GH  [NN*192];
__device__ float  g_HB0 [NN*64];
__device__ float  g_HB1 [NN*64];
__device__ float4 g_SSRC0[ROWS];
__device__ float4 g_SDST0[ROWS];
__device__ float4 g_SSRC1[ROWS];
__device__ float4 g_SDST1[ROWS];
__device__ float4 g_ALPHA[TT*EP];
__device__ int    g_CNT [NN];
__device__ int    g_ROWP[NN+1];
__device__ int    g_CUR [NN];
__device__ int    g_COL [EP];
__device__ int    g_EID [EP];

// ---------------- small helpers ----------------
__device__ __forceinline__ float lrelu(float x){ return x > 0.f ? x : 0.2f*x; }
__device__ __forceinline__ float eluf (float x){ return x > 0.f ? x : expm1f(x); }
__device__ __forceinline__ float sigm (float x){ return 1.f/(1.f+__expf(-x)); }
__device__ __forceinline__ float pick4(float4 a,int h){
    return h==0?a.x : (h==1?a.y : (h==2?a.z : a.w));
}

// ---------------- CSR build ----------------
__global__ void k_zero_cnt(){ int i=blockIdx.x*blockDim.x+threadIdx.x; if(i<NN) g_CNT[i]=0; }
__global__ void k_zero_h0 (){ int i=blockIdx.x*blockDim.x+threadIdx.x; if(i<NN*64) g_HB0[i]=0.f; }

__global__ void k_hist(const int* __restrict__ ei){
    int e = blockIdx.x*blockDim.x+threadIdx.x;
    if(e>=EP) return;
    int d = (e<EE) ? ei[EE+e] : (e-EE);
    atomicAdd(&g_CNT[d],1);
}

__global__ void k_scan(){
    __shared__ int sm[1024];
    __shared__ int s_carry;
    int tid = threadIdx.x;
    if(tid==0) s_carry = 0;
    __syncthreads();
    for(int base=0; base<NN; base+=1024){
        int i = base+tid;
        int v = (i<NN) ? g_CNT[i] : 0;
        sm[tid]=v; __syncthreads();
        for(int off=1; off<1024; off<<=1){
            int add = (tid>=off) ? sm[tid-off] : 0;
            __syncthreads();
            sm[tid]+=add;
            __syncthreads();
        }
        int incl  = sm[tid];
        int carry = s_carry;
        if(i<NN){
            int excl = carry + incl - v;
            g_ROWP[i]=excl;
            g_CUR [i]=excl;
        }
        __syncthreads();
        if(tid==1023) s_carry = carry + sm[1023];
        __syncthreads();
    }
    if(tid==0) g_ROWP[NN]=s_carry;
}

__global__ void k_scatter(const int* __restrict__ ei){
    int e = blockIdx.x*blockDim.x+threadIdx.x;
    if(e>=EP) return;
    int s,d;
    if(e<EE){ s=ei[e]; d=ei[EE+e]; } else { s=d=e-EE; }
    int p = atomicAdd(&g_CUR[d],1);
    g_COL[p]=s; g_EID[p]=e;
}

// ---------------- x transpose: [N,T,F] -> [T,N,F] ----------------
__global__ void k_transpose(const float* __restrict__ x){
    int idx = blockIdx.x*blockDim.x+threadIdx.x;
    if(idx >= ROWS*16) return;
    int i = idx>>4, q = idx&15;
    int t = i/NN, n = i - t*NN;
    float4 v = *(const float4*)&x[((size_t)n*TT + t)*64 + q*4];
    *(float4*)&g_XT[(size_t)i*64 + q*4] = v;
}

// ---------------- generic GEMM: C[M,Nc] = A[M,64] @ B(64,Nc) ----------------
// TRANSB: B given as [Nc,64] row-major (i.e. use B^T)
template<bool TRANSB>
__global__ void gemm64(const float* __restrict__ A, const float* __restrict__ B,
                       float* __restrict__ C, int M, int Nc){
    __shared__ __align__(16) float As[64*68];
    __shared__ __align__(16) float Bs[64*68];
    int m0 = blockIdx.x*64, n0 = blockIdx.y*64;
    int tid = threadIdx.x;

    #pragma unroll
    for(int j=0;j<4;j++){
        int idx = tid + j*256;
        int r = idx>>4, kq = (idx&15)*4;
        float4 v = make_float4(0.f,0.f,0.f,0.f);
        if(m0+r < M) v = *(const float4*)&A[(size_t)(m0+r)*64 + kq];
        As[(kq+0)*68+r]=v.x; As[(kq+1)*68+r]=v.y;
        As[(kq+2)*68+r]=v.z; As[(kq+3)*68+r]=v.w;
    }
    if(!TRANSB){
        #pragma unroll
        for(int j=0;j<4;j++){
            int idx = tid + j*256;
            int k = idx>>4, nq=(idx&15)*4;
            float4 v = *(const float4*)&B[(size_t)k*Nc + n0 + nq];
            *(float4*)&Bs[k*68+nq] = v;
        }
    } else {
        #pragma unroll
        for(int j=0;j<4;j++){
            int idx = tid + j*256;
            int n = idx>>4, kq=(idx&15)*4;
            float4 v = *(const float4*)&B[(size_t)(n0+n)*64 + kq];
            Bs[(kq+0)*68+n]=v.x; Bs[(kq+1)*68+n]=v.y;
            Bs[(kq+2)*68+n]=v.z; Bs[(kq+3)*68+n]=v.w;
        }
    }
    __syncthreads();

    int ty = tid>>4, tx = tid&15;
    float acc[4][4];
    #pragma unroll
    for(int r=0;r<4;r++)
        #pragma unroll
        for(int c=0;c<4;c++) acc[r][c]=0.f;

    #pragma unroll
    for(int k=0;k<64;k++){
        float4 a = *(float4*)&As[k*68 + ty*4];
        float4 b = *(float4*)&Bs[k*68 + tx*4];
        acc[0][0]+=a.x*b.x; acc[0][1]+=a.x*b.y; acc[0][2]+=a.x*b.z; acc[0][3]+=a.x*b.w;
        acc[1][0]+=a.y*b.x; acc[1][1]+=a.y*b.y; acc[1][2]+=a.y*b.z; acc[1][3]+=a.y*b.w;
        acc[2][0]+=a.z*b.x; acc[2][1]+=a.z*b.y; acc[2][2]+=a.z*b.z; acc[2][3]+=a.z*b.w;
        acc[3][0]+=a.w*b.x; acc[3][1]+=a.w*b.y; acc[3][2]+=a.w*b.z; acc[3][3]+=a.w*b.w;
    }
    #pragma unroll
    for(int r=0;r<4;r++){
        int m = m0 + ty*4 + r;
        if(m < M){
            *(float4*)&C[(size_t)m*Nc + n0 + tx*4] =
                make_float4(acc[r][0],acc[r][1],acc[r][2],acc[r][3]);
        }
    }
}

// ---------------- per-row attention scalars: s[i,h] = sum_c xw[i,h*C+c]*a[h,c] ----------------
template<int C,int HC>
__global__ void k_svals(const float* __restrict__ XW,
                        const float* __restrict__ asrc, const float* __restrict__ adst,
                        float4* __restrict__ SS, float4* __restrict__ SD){
    int w = (blockIdx.x*blockDim.x+threadIdx.x)>>5;
    if(w>=ROWS) return;
    int lane = threadIdx.x&31;
    float s0=0,s1=0,s2=0,s3=0,d0=0,d1=0,d2=0,d3=0;
    const float* row = XW + (size_t)w*HC;
    #pragma unroll
    for(int it=0; it<HC/32; it++){
        int idx = lane + it*32;
        float v  = row[idx];
        float as = asrc[idx], ad = adst[idx];
        int h = idx / C;
        if(h==0){ s0+=v*as; d0+=v*ad; }
        else if(h==1){ s1+=v*as; d1+=v*ad; }
        else if(h==2){ s2+=v*as; d2+=v*ad; }
        else { s3+=v*as; d3+=v*ad; }
    }
    #pragma unroll
    for(int off=16; off; off>>=1){
        s0+=__shfl_xor_sync(0xffffffffu,s0,off); s1+=__shfl_xor_sync(0xffffffffu,s1,off);
        s2+=__shfl_xor_sync(0xffffffffu,s2,off); s3+=__shfl_xor_sync(0xffffffffu,s3,off);
        d0+=__shfl_xor_sync(0xffffffffu,d0,off); d1+=__shfl_xor_sync(0xffffffffu,d1,off);
        d2+=__shfl_xor_sync(0xffffffffu,d2,off); d3+=__shfl_xor_sync(0xffffffffu,d3,off);
    }
    if(lane==0){ SS[w]=make_float4(s0,s1,s2,s3); SD[w]=make_float4(d0,d1,d2,d3); }
}

// ---------------- segment softmax (alpha), warp per (t,node) ----------------
__global__ void k_alpha(const float4* __restrict__ SS, const float4* __restrict__ SD,
                        float* __restrict__ out_alpha /* null or d_out+OFF_A */){
    int w = (blockIdx.x*blockDim.x+threadIdx.x)>>5;
    if(w>=ROWS) return;
    int lane = threadIdx.x&31;
    int t = w/NN, n = w - t*NN;
    int beg = g_ROWP[n], end = g_ROWP[n+1];
    float4 sd = SD[w];
    const float4* ss = SS + (size_t)t*NN;

    float m0=-1e30f,m1=-1e30f,m2=-1e30f,m3=-1e30f;
    for(int b=beg; b<end; b+=32){
        int e=b+lane;
        if(e<end){
            float4 s = ss[g_COL[e]];
            m0=fmaxf(m0,lrelu(s.x+sd.x)); m1=fmaxf(m1,lrelu(s.y+sd.y));
            m2=fmaxf(m2,lrelu(s.z+sd.z)); m3=fmaxf(m3,lrelu(s.w+sd.w));
        }
    }
    #pragma unroll
    for(int off=16; off; off>>=1){
        m0=fmaxf(m0,__shfl_xor_sync(0xffffffffu,m0,off));
        m1=fmaxf(m1,__shfl_xor_sync(0xffffffffu,m1,off));
        m2=fmaxf(m2,__shfl_xor_sync(0xffffffffu,m2,off));
        m3=fmaxf(m3,__shfl_xor_sync(0xffffffffu,m3,off));
    }
    float q0=0,q1=0,q2=0,q3=0;
    for(int b=beg; b<end; b+=32){
        int e=b+lane;
        if(e<end){
            float4 s = ss[g_COL[e]];
            q0+=__expf(lrelu(s.x+sd.x)-m0); q1+=__expf(lrelu(s.y+sd.y)-m1);
            q2+=__expf(lrelu(s.z+sd.z)-m2); q3+=__expf(lrelu(s.w+sd.w)-m3);
        }
    }
    #pragma unroll
    for(int off=16; off; off>>=1){
        q0+=__shfl_xor_sync(0xffffffffu,q0,off); q1+=__shfl_xor_sync(0xffffffffu,q1,off);
        q2+=__shfl_xor_sync(0xffffffffu,q2,off); q3+=__shfl_xor_sync(0xffffffffu,q3,off);
    }
    float i0=1.f/(q0+1e-16f), i1=1.f/(q1+1e-16f), i2=1.f/(q2+1e-16f), i3=1.f/(q3+1e-16f);
    bool wo = (out_alpha != nullptr) && (t == TT-1);
    for(int b=beg; b<end; b+=32){
        int e=b+lane;
        if(e<end){
            float4 s = ss[g_COL[e]];
            float4 a;
            a.x = __expf(lrelu(s.x+sd.x)-m0)*i0;
            a.y = __expf(lrelu(s.y+sd.y)-m1)*i1;
            a.z = __expf(lrelu(s.z+sd.z)-m2)*i2;
            a.w = __expf(lrelu(s.w+sd.w)-m3)*i3;
            g_ALPHA[(size_t)t*EP + e] = a;
            if(wo) ((float4*)out_alpha)[g_EID[e]] = a;
        }
    }
}

// ---------------- layer-0 aggregate (+b0, ELU) -> H0 ----------------
__global__ void k_agg0(const float* __restrict__ b0v){
    int w = (blockIdx.x*blockDim.x+threadIdx.x)>>5;
    if(w>=ROWS) return;
    int lane = threadIdx.x&31;
    int t = w/NN, n = w - t*NN;
    int beg = g_ROWP[n], end = g_ROWP[n+1];
    int c0 = 2*lane, h = lane>>3;
    const float*  xw = g_XW0  + (size_t)t*NN*64;
    const float4* al = g_ALPHA + (size_t)t*EP;
    float ax=0.f, ay=0.f;
    for(int e=beg; e<end; e++){
        float4 a = al[e];
        float ah = pick4(a,h);
        int cs = g_COL[e];
        float2 v = *(const float2*)&xw[(size_t)cs*64 + c0];
        ax += ah*v.x; ay += ah*v.y;
    }
    ax = eluf(ax + b0v[c0]); ay = eluf(ay + b0v[c0+1]);
    *(float2*)&g_H0[(size_t)w*64 + c0] = make_float2(ax,ay);
}

// ---------------- layer-1 aggregate (mean heads, +b1, ELU, LayerNorm) -> HS ----------------
__global__ void k_agg1(const float* __restrict__ b1v,
                       const float* __restrict__ lng, const float* __restrict__ lnb){
    int w = (blockIdx.x*blockDim.x+threadIdx.x)>>5;
    if(w>=ROWS) return;
    int lane = threadIdx.x&31;
    int t = w/NN, n = w - t*NN;
    int beg = g_ROWP[n], end = g_ROWP[n+1];
    int c0 = 2*lane;
    const float*  xw = g_XW1  + (size_t)t*NN*256;
    const float4* al = g_ALPHA + (size_t)t*EP;
    float a0x=0,a0y=0,a1x=0,a1y=0,a2x=0,a2y=0,a3x=0,a3y=0;
    for(int e=beg; e<end; e++){
        float4 a = al[e];
        int cs = g_COL[e];
        const float* r = xw + (size_t)cs*256;
        float2 v0 = *(const float2*)&r[      c0];
        float2 v1 = *(const float2*)&r[ 64 + c0];
        float2 v2 = *(const float2*)&r[128 + c0];
        float2 v3 = *(const float2*)&r[192 + c0];
        a0x += a.x*v0.x; a0y += a.x*v0.y;
        a1x += a.y*v1.x; a1y += a.y*v1.y;
        a2x += a.z*v2.x; a2y += a.z*v2.y;
        a3x += a.w*v3.x; a3y += a.w*v3.y;
    }
    float vx = (a0x+a1x+a2x+a3x)*0.25f + b1v[c0];
    float vy = (a0y+a1y+a2y+a3y)*0.25f + b1v[c0+1];
    vx = eluf(vx); vy = eluf(vy);
    float s  = vx+vy;
    float s2 = vx*vx + vy*vy;
    #pragma unroll
    for(int off=16; off; off>>=1){
        s  += __shfl_xor_sync(0xffffffffu,s ,off);
        s2 += __shfl_xor_sync(0xffffffffu,s2,off);
    }
    float mu   = s*(1.f/64.f);
    float var  = fmaxf(s2*(1.f/64.f) - mu*mu, 0.f);
    float rstd = rsqrtf(var + 1e-5f);
    float ox = (vx-mu)*rstd*lng[c0]   + lnb[c0];
    float oy = (vy-mu)*rstd*lng[c0+1] + lnb[c0+1];
    *(float2*)&g_HS[(size_t)w*64 + c0] = make_float2(ox,oy);
}

// ---------------- GRU elementwise gates ----------------
__global__ void k_gru(const float* __restrict__ gi,
                      const float* __restrict__ bih, const float* __restrict__ bhh,
                      const float* __restrict__ hin, float* __restrict__ hout){
    int idx = blockIdx.x*blockDim.x+threadIdx.x;
    if(idx >= NN*64) return;
    int n = idx>>6, j = idx&63;
    const float* gn = gi   + (size_t)n*192;
    const float* hn = g_GH + (size_t)n*192;
    float r = sigm(gn[j]      + bih[j]      + hn[j]      + bhh[j]);
    float z = sigm(gn[64+j]   + bih[64+j]   + hn[64+j]   + bhh[64+j]);
    float g = tanhf(gn[128+j] + bih[128+j]  + r*(hn[128+j] + bhh[128+j]));
    float h = hin[idx];
    hout[idx] = (1.f-z)*g + z*h;
}

// ---------------- edge-index output ----------------
__global__ void k_eout(const int* __restrict__ ei, float* __restrict__ out){
    int idx = blockIdx.x*blockDim.x+threadIdx.x;
    if(idx >= 2*EP) return;
    int row = idx/EP, e = idx - row*EP;
    int v = (e<EE) ? ei[row*EE + e] : (e-EE);
    out[idx] = (float)v;
}

// ---------------- host launcher ----------------
extern "C" void kernel_launch(void* const* d_in, const int* in_sizes, int n_in,
                              void* d_out, int out_size){
    const float* x    = (const float*)d_in[0];
    const int*   ei   = (const int*)  d_in[1];
    const float* W0   = (const float*)d_in[2];
    const float* as0  = (const float*)d_in[3];
    const float* ad0  = (const float*)d_in[4];
    const float* b0   = (const float*)d_in[5];
    const float* W1   = (const float*)d_in[6];
    const float* as1  = (const float*)d_in[7];
    const float* ad1  = (const float*)d_in[8];
    const float* b1   = (const float*)d_in[9];
    const float* lng  = (const float*)d_in[10];
    const float* lnb  = (const float*)d_in[11];
    const float* Wih  = (const float*)d_in[12];
    const float* Whh  = (const float*)d_in[13];
    const float* bih  = (const float*)d_in[14];
    const float* bhh  = (const float*)d_in[15];
    float* out = (float*)d_out;

    const int OFF_A  = NN*64;            // 640000
    const int OFF_EI = OFF_A + EP*4;     // 1320000

    float *pXT,*pXW0,*pH0,*pXW1,*pHS,*pGI,*pGH,*pHB0,*pHB1;
    float4 *pSS0,*pSD0,*pSS1,*pSD1;
    cudaGetSymbolAddress((void**)&pXT , g_XT );
    cudaGetSymbolAddress((void**)&pXW0, g_XW0);
    cudaGetSymbolAddress((void**)&pH0 , g_H0 );
    cudaGetSymbolAddress((void**)&pXW1, g_XW1);
    cudaGetSymbolAddress((void**)&pHS , g_HS );
    cudaGetSymbolAddress((void**)&pGI , g_GI );
    cudaGetSymbolAddress((void**)&pGH , g_GH );
    cudaGetSymbolAddress((void**)&pHB0, g_HB0);
    cudaGetSymbolAddress((void**)&pHB1, g_HB1);
    cudaGetSymbolAddress((void**)&pSS0, g_SSRC0);
    cudaGetSymbolAddress((void**)&pSD0, g_SDST0);
    cudaGetSymbolAddress((void**)&pSS1, g_SSRC1);
    cudaGetSymbolAddress((void**)&pSD1, g_SDST1);

    const int WB = 7500;  // ROWS warps @ 8 warps/block

    // CSR build + init
    k_zero_cnt<<<(NN+255)/256,256>>>();
    k_zero_h0 <<<(NN*64+255)/256,256>>>();
    k_hist    <<<(EP+255)/256,256>>>(ei);
    k_scan    <<<1,1024>>>();
    k_scatter <<<(EP+255)/256,256>>>(ei);

    // layer 0
    k_transpose<<<(ROWS*16+255)/256,256>>>(x);
    gemm64<false><<<dim3(938,1),256>>>(pXT, W0, pXW0, ROWS, 64);
    k_svals<16,64><<<WB,256>>>(pXW0, as0, ad0, pSS0, pSD0);
    k_alpha<<<WB,256>>>(pSS0, pSD0, nullptr);
    k_agg0 <<<WB,256>>>(b0);

    // layer 1
    gemm64<false><<<dim3(938,4),256>>>(pH0, W1, pXW1, ROWS, 256);
    k_svals<64,256><<<WB,256>>>(pXW1, as1, ad1, pSS1, pSD1);
    k_alpha<<<WB,256>>>(pSS1, pSD1, out + OFF_A);
    k_agg1 <<<WB,256>>>(b1, lng, lnb);

    // GRU
    gemm64<true><<<dim3(938,3),256>>>(pHS, Wih, pGI, ROWS, 192);
    for(int t=0; t<TT; t++){
        const float* hin = (t&1) ? pHB1 : pHB0;
        float* hout = (t==TT-1) ? out : ((t&1) ? pHB0 : pHB1);
        gemm64<true><<<dim3(157,3),256>>>(hin, Whh, pGH, NN, 192);
        k_gru<<<(NN*64+255)/256,256>>>(pGI + (size_t)t*NN*192, bih, bhh, hin, hout);
    }

    // edge index output
    k_eout<<<(2*EP+255)/256,256>>>(ei, out + OFF_EI);
    (void)in_sizes; (void)n_in; (void)out_size;
}

// round 4
// speedup vs baseline: 1.6126x; 1.6126x over previous
#include <cuda_runtime.h>
#include <cuda_fp16.h>
#include <math.h>

// ---------------- problem constants ----------------
#define NN   10000
#define TT   6
#define HIDD 64
#define EE   160000
#define EP   170000          // EE + NN self loops
#define ROWS (TT*NN)         // 60000

// ---------------- scratch (__device__ globals; no allocations) ----------------
__device__ float  g_XW0 [ROWS*64];
__device__ float  g_H0  [ROWS*64];
__device__ float  g_XW1 [ROWS*256];
__device__ __half g_XW0h[ROWS*64];
__device__ __half g_XW1h[ROWS*256];
__device__ float  g_HS  [ROWS*64];
__device__ float  g_GI  [ROWS*192];
__device__ float  g_HB0 [NN*64];
__device__ float  g_HB1 [NN*64];
__device__ float4 g_SSRC0[ROWS];
__device__ float4 g_SDST0[ROWS];
__device__ float4 g_SSRC1[ROWS];
__device__ float4 g_SDST1[ROWS];
__device__ float4 g_ALPHA[TT*EP];
__device__ int    g_CNT [NN];
__device__ int    g_ROWP[NN+1];
__device__ int    g_CUR [NN];
__device__ int    g_COL [EP];
__device__ int    g_EID [EP];

// ---------------- small helpers ----------------
__device__ __forceinline__ float lrelu(float x){ return x > 0.f ? x : 0.2f*x; }
__device__ __forceinline__ float eluf (float x){ return x > 0.f ? x : expm1f(x); }
__device__ __forceinline__ float sigm (float x){ return 1.f/(1.f+__expf(-x)); }
__device__ __forceinline__ float pick4(float4 a,int h){
    return h==0?a.x : (h==1?a.y : (h==2?a.z : a.w));
}

// ---------------- CSR build ----------------
__global__ void k_zero_cnt(){ int i=blockIdx.x*blockDim.x+threadIdx.x; if(i<NN) g_CNT[i]=0; }
__global__ void k_zero_h0 (){ int i=blockIdx.x*blockDim.x+threadIdx.x; if(i<NN*64) g_HB0[i]=0.f; }

__global__ void k_hist(const int* __restrict__ ei){
    int e = blockIdx.x*blockDim.x+threadIdx.x;
    if(e>=EP) return;
    int d = (e<EE) ? ei[EE+e] : (e-EE);
    atomicAdd(&g_CNT[d],1);
}

// warp-shuffle hierarchical scan, 1 block of 1024
__global__ void k_scan(){
    __shared__ int warpsum[32];
    __shared__ int s_carry;
    int tid = threadIdx.x, lane = tid&31, wid = tid>>5;
    if(tid==0) s_carry = 0;
    __syncthreads();
    for(int base=0; base<NN; base+=1024){
        int i = base+tid;
        int v = (i<NN) ? g_CNT[i] : 0;
        int x = v;
        #pragma unroll
        for(int off=1; off<32; off<<=1){
            int y = __shfl_up_sync(0xffffffffu, x, off);
            if(lane>=off) x += y;
        }
        if(lane==31) warpsum[wid] = x;
        __syncthreads();
        if(wid==0){
            int w = warpsum[lane];
            #pragma unroll
            for(int off=1; off<32; off<<=1){
                int y = __shfl_up_sync(0xffffffffu, w, off);
                if(lane>=off) w += y;
            }
            warpsum[lane] = w;
        }
        __syncthreads();
        int incl  = x + (wid ? warpsum[wid-1] : 0);
        int carry = s_carry;
        if(i<NN){
            int excl = carry + incl - v;
            g_ROWP[i]=excl; g_CUR[i]=excl;
        }
        __syncthreads();
        if(tid==1023) s_carry = carry + incl;
        __syncthreads();
    }
    if(tid==0) g_ROWP[NN]=s_carry;
}

__global__ void k_scatter(const int* __restrict__ ei){
    int e = blockIdx.x*blockDim.x+threadIdx.x;
    if(e>=EP) return;
    int s,d;
    if(e<EE){ s=ei[e]; d=ei[EE+e]; } else { s=d=e-EE; }
    int p = atomicAdd(&g_CUR[d],1);
    g_COL[p]=s; g_EID[p]=e;
}

// ---------------- generic GEMM: C[M,Nc] = A[M,64] @ B(64,Nc) ----------------
// TRANSB: B given as [Nc,64] row-major (use B^T)
// XMAP:   A row i maps to x[((i%NN)*TT + i/NN)*64]  (implicit [N,T,F]->[T,N,F])
// Ch:     optional fp16 copy of C
template<bool TRANSB, bool XMAP>
__global__ void gemm64(const float* __restrict__ A, const float* __restrict__ B,
                       float* __restrict__ C, __half* __restrict__ Ch, int M, int Nc){
    __shared__ __align__(16) float As[64*68];
    __shared__ __align__(16) float Bs[64*68];
    int m0 = blockIdx.x*64, n0 = blockIdx.y*64;
    int tid = threadIdx.x;

    #pragma unroll
    for(int j=0;j<4;j++){
        int idx = tid + j*256;
        int r = idx>>4, kq = (idx&15)*4;
        float4 v = make_float4(0.f,0.f,0.f,0.f);
        int i = m0+r;
        if(i < M){
            size_t off;
            if(XMAP){ int t=i/NN, n=i-t*NN; off=((size_t)n*TT+t)*64 + kq; }
            else     { off=(size_t)i*64 + kq; }
            v = *(const float4*)&A[off];
        }
        As[(kq+0)*68+r]=v.x; As[(kq+1)*68+r]=v.y;
        As[(kq+2)*68+r]=v.z; As[(kq+3)*68+r]=v.w;
    }
    if(!TRANSB){
        #pragma unroll
        for(int j=0;j<4;j++){
            int idx = tid + j*256;
            int k = idx>>4, nq=(idx&15)*4;
            float4 v = *(const float4*)&B[(size_t)k*Nc + n0 + nq];
            *(float4*)&Bs[k*68+nq] = v;
        }
    } else {
        #pragma unroll
        for(int j=0;j<4;j++){
            int idx = tid + j*256;
            int n = idx>>4, kq=(idx&15)*4;
            float4 v = *(const float4*)&B[(size_t)(n0+n)*64 + kq];
            Bs[(kq+0)*68+n]=v.x; Bs[(kq+1)*68+n]=v.y;
            Bs[(kq+2)*68+n]=v.z; Bs[(kq+3)*68+n]=v.w;
        }
    }
    __syncthreads();

    int ty = tid>>4, tx = tid&15;
    float acc[4][4];
    #pragma unroll
    for(int r=0;r<4;r++)
        #pragma unroll
        for(int c=0;c<4;c++) acc[r][c]=0.f;

    #pragma unroll
    for(int k=0;k<64;k++){
        float4 a = *(float4*)&As[k*68 + ty*4];
        float4 b = *(float4*)&Bs[k*68 + tx*4];
        acc[0][0]+=a.x*b.x; acc[0][1]+=a.x*b.y; acc[0][2]+=a.x*b.z; acc[0][3]+=a.x*b.w;
        acc[1][0]+=a.y*b.x; acc[1][1]+=a.y*b.y; acc[1][2]+=a.y*b.z; acc[1][3]+=a.y*b.w;
        acc[2][0]+=a.z*b.x; acc[2][1]+=a.z*b.y; acc[2][2]+=a.z*b.z; acc[2][3]+=a.z*b.w;
        acc[3][0]+=a.w*b.x; acc[3][1]+=a.w*b.y; acc[3][2]+=a.w*b.z; acc[3][3]+=a.w*b.w;
    }
    #pragma unroll
    for(int r=0;r<4;r++){
        int m = m0 + ty*4 + r;
        if(m < M){
            size_t o = (size_t)m*Nc + n0 + tx*4;
            *(float4*)&C[o] = make_float4(acc[r][0],acc[r][1],acc[r][2],acc[r][3]);
            if(Ch){
                __half2* p = (__half2*)&Ch[o];
                p[0] = __floats2half2_rn(acc[r][0],acc[r][1]);
                p[1] = __floats2half2_rn(acc[r][2],acc[r][3]);
            }
        }
    }
}

// ---------------- per-row attention scalars ----------------
template<int C,int HC>
__global__ void k_svals(const float* __restrict__ XW,
                        const float* __restrict__ asrc, const float* __restrict__ adst,
                        float4* __restrict__ SS, float4* __restrict__ SD){
    int w = (blockIdx.x*blockDim.x+threadIdx.x)>>5;
    if(w>=ROWS) return;
    int lane = threadIdx.x&31;
    float s0=0,s1=0,s2=0,s3=0,d0=0,d1=0,d2=0,d3=0;
    const float* row = XW + (size_t)w*HC;
    #pragma unroll
    for(int it=0; it<HC/32; it++){
        int idx = lane + it*32;
        float v  = row[idx];
        float as = asrc[idx], ad = adst[idx];
        int h = idx / C;
        if(h==0){ s0+=v*as; d0+=v*ad; }
        else if(h==1){ s1+=v*as; d1+=v*ad; }
        else if(h==2){ s2+=v*as; d2+=v*ad; }
        else { s3+=v*as; d3+=v*ad; }
    }
    #pragma unroll
    for(int off=16; off; off>>=1){
        s0+=__shfl_xor_sync(0xffffffffu,s0,off); s1+=__shfl_xor_sync(0xffffffffu,s1,off);
        s2+=__shfl_xor_sync(0xffffffffu,s2,off); s3+=__shfl_xor_sync(0xffffffffu,s3,off);
        d0+=__shfl_xor_sync(0xffffffffu,d0,off); d1+=__shfl_xor_sync(0xffffffffu,d1,off);
        d2+=__shfl_xor_sync(0xffffffffu,d2,off); d3+=__shfl_xor_sync(0xffffffffu,d3,off);
    }
    if(lane==0){ SS[w]=make_float4(s0,s1,s2,s3); SD[w]=make_float4(d0,d1,d2,d3); }
}

// ---------------- segment softmax (alpha), warp per (t,node) ----------------
__global__ void k_alpha(const float4* __restrict__ SS, const float4* __restrict__ SD,
                        float* __restrict__ out_alpha){
    int w = (blockIdx.x*blockDim.x+threadIdx.x)>>5;
    if(w>=ROWS) return;
    int lane = threadIdx.x&31;
    int t = w/NN, n = w - t*NN;
    int beg = g_ROWP[n], end = g_ROWP[n+1];
    float4 sd = SD[w];
    const float4* ss = SS + (size_t)t*NN;

    float m0=-1e30f,m1=-1e30f,m2=-1e30f,m3=-1e30f;
    for(int b=beg; b<end; b+=32){
        int e=b+lane;
        if(e<end){
            float4 s = ss[g_COL[e]];
            m0=fmaxf(m0,lrelu(s.x+sd.x)); m1=fmaxf(m1,lrelu(s.y+sd.y));
            m2=fmaxf(m2,lrelu(s.z+sd.z)); m3=fmaxf(m3,lrelu(s.w+sd.w));
        }
    }
    #pragma unroll
    for(int off=16; off; off>>=1){
        m0=fmaxf(m0,__shfl_xor_sync(0xffffffffu,m0,off));
        m1=fmaxf(m1,__shfl_xor_sync(0xffffffffu,m1,off));
        m2=fmaxf(m2,__shfl_xor_sync(0xffffffffu,m2,off));
        m3=fmaxf(m3,__shfl_xor_sync(0xffffffffu,m3,off));
    }
    float q0=0,q1=0,q2=0,q3=0;
    for(int b=beg; b<end; b+=32){
        int e=b+lane;
        if(e<end){
            float4 s = ss[g_COL[e]];
            q0+=__expf(lrelu(s.x+sd.x)-m0); q1+=__expf(lrelu(s.y+sd.y)-m1);
            q2+=__expf(lrelu(s.z+sd.z)-m2); q3+=__expf(lrelu(s.w+sd.w)-m3);
        }
    }
    #pragma unroll
    for(int off=16; off; off>>=1){
        q0+=__shfl_xor_sync(0xffffffffu,q0,off); q1+=__shfl_xor_sync(0xffffffffu,q1,off);
        q2+=__shfl_xor_sync(0xffffffffu,q2,off); q3+=__shfl_xor_sync(0xffffffffu,q3,off);
    }
    float i0=1.f/(q0+1e-16f), i1=1.f/(q1+1e-16f), i2=1.f/(q2+1e-16f), i3=1.f/(q3+1e-16f);
    bool wo = (out_alpha != nullptr) && (t == TT-1);
    for(int b=beg; b<end; b+=32){
        int e=b+lane;
        if(e<end){
            float4 s = ss[g_COL[e]];
            float4 a;
            a.x = __expf(lrelu(s.x+sd.x)-m0)*i0;
            a.y = __expf(lrelu(s.y+sd.y)-m1)*i1;
            a.z = __expf(lrelu(s.z+sd.z)-m2)*i2;
            a.w = __expf(lrelu(s.w+sd.w)-m3)*i3;
            g_ALPHA[(size_t)t*EP + e] = a;
            if(wo) ((float4*)out_alpha)[g_EID[e]] = a;
        }
    }
}

// ---------------- layer-0 aggregate (+b0, ELU) -> H0 (fp16 gather) ----------------
__global__ void k_agg0(const float* __restrict__ b0v){
    int w = (blockIdx.x*blockDim.x+threadIdx.x)>>5;
    if(w>=ROWS) return;
    int lane = threadIdx.x&31;
    int t = w/NN, n = w - t*NN;
    int beg = g_ROWP[n], end = g_ROWP[n+1];
    int c0 = 2*lane, h = lane>>3;
    const __half*  xw = g_XW0h + (size_t)t*NN*64;
    const float4*  al = g_ALPHA + (size_t)t*EP;
    float ax=0.f, ay=0.f;
    for(int e=beg; e<end; e++){
        float4 a = al[e];
        float ah = pick4(a,h);
        int cs = g_COL[e];
        float2 v = __half22float2(*(const __half2*)&xw[(size_t)cs*64 + c0]);
        ax += ah*v.x; ay += ah*v.y;
    }
    ax = eluf(ax + b0v[c0]); ay = eluf(ay + b0v[c0+1]);
    *(float2*)&g_H0[(size_t)w*64 + c0] = make_float2(ax,ay);
}

// ---------------- layer-1 aggregate (mean heads, +b1, ELU, LayerNorm) -> HS ----------------
__global__ void k_agg1(const float* __restrict__ b1v,
                       const float* __restrict__ lng, const float* __restrict__ lnb){
    int w = (blockIdx.x*blockDim.x+threadIdx.x)>>5;
    if(w>=ROWS) return;
    int lane = threadIdx.x&31;
    int t = w/NN, n = w - t*NN;
    int beg = g_ROWP[n], end = g_ROWP[n+1];
    int c0 = 2*lane;
    const __half*  xw = g_XW1h + (size_t)t*NN*256;
    const float4*  al = g_ALPHA + (size_t)t*EP;
    float a0x=0,a0y=0,a1x=0,a1y=0,a2x=0,a2y=0,a3x=0,a3y=0;
    for(int e=beg; e<end; e++){
        float4 a = al[e];
        int cs = g_COL[e];
        const __half* r = xw + (size_t)cs*256;
        float2 v0 = __half22float2(*(const __half2*)&r[      c0]);
        float2 v1 = __half22float2(*(const __half2*)&r[ 64 + c0]);
        float2 v2 = __half22float2(*(const __half2*)&r[128 + c0]);
        float2 v3 = __half22float2(*(const __half2*)&r[192 + c0]);
        a0x += a.x*v0.x; a0y += a.x*v0.y;
        a1x += a.y*v1.x; a1y += a.y*v1.y;
        a2x += a.z*v2.x; a2y += a.z*v2.y;
        a3x += a.w*v3.x; a3y += a.w*v3.y;
    }
    float vx = (a0x+a1x+a2x+a3x)*0.25f + b1v[c0];
    float vy = (a0y+a1y+a2y+a3y)*0.25f + b1v[c0+1];
    vx = eluf(vx); vy = eluf(vy);
    float s  = vx+vy;
    float s2 = vx*vx + vy*vy;
    #pragma unroll
    for(int off=16; off; off>>=1){
        s  += __shfl_xor_sync(0xffffffffu,s ,off);
        s2 += __shfl_xor_sync(0xffffffffu,s2,off);
    }
    float mu   = s*(1.f/64.f);
    float var  = fmaxf(s2*(1.f/64.f) - mu*mu, 0.f);
    float rstd = rsqrtf(var + 1e-5f);
    float ox = (vx-mu)*rstd*lng[c0]   + lnb[c0];
    float oy = (vy-mu)*rstd*lng[c0+1] + lnb[c0+1];
    *(float2*)&g_HS[(size_t)w*64 + c0] = make_float2(ox,oy);
}

// ---------------- fused GRU step: gh GEMM + gates ----------------
// block: 256 thr, 64 rows x 192 cols tile; dynamic smem As[64*68] + Bs[64*196]
__global__ void k_gru_fused(const float* __restrict__ hin, const float* __restrict__ gi,
                            const float* __restrict__ Whh,
                            const float* __restrict__ bih, const float* __restrict__ bhh,
                            float* __restrict__ hout){
    extern __shared__ float sm[];
    float* As = sm;                 // [64k][68]
    float* Bs = sm + 64*68;         // [64k][196] cols j=0..191
    int m0 = blockIdx.x*64, tid = threadIdx.x;

    #pragma unroll
    for(int j=0;j<4;j++){
        int idx = tid + j*256;
        int r = idx>>4, kq=(idx&15)*4;
        float4 v = make_float4(0.f,0.f,0.f,0.f);
        if(m0+r < NN) v = *(const float4*)&hin[(size_t)(m0+r)*64 + kq];
        As[(kq+0)*68+r]=v.x; As[(kq+1)*68+r]=v.y;
        As[(kq+2)*68+r]=v.z; As[(kq+3)*68+r]=v.w;
    }
    #pragma unroll
    for(int j=0;j<12;j++){
        int idx = tid + j*256;      // 3072 float4 = 192 rows * 16
        int row = idx>>4, kq=(idx&15)*4;
        float4 v = *(const float4*)&Whh[(size_t)row*64 + kq];
        Bs[(kq+0)*196+row]=v.x; Bs[(kq+1)*196+row]=v.y;
        Bs[(kq+2)*196+row]=v.z; Bs[(kq+3)*196+row]=v.w;
    }
    __syncthreads();

    int ty = tid>>4, tx = tid&15;
    float ar[4][4], az[4][4], ag[4][4];
    #pragma unroll
    for(int r=0;r<4;r++)
        #pragma unroll
        for(int c=0;c<4;c++){ ar[r][c]=0.f; az[r][c]=0.f; ag[r][c]=0.f; }

    #pragma unroll
    for(int k=0;k<64;k++){
        float4 a  = *(float4*)&As[k*68 + ty*4];
        float4 br = *(float4*)&Bs[k*196 +       tx*4];
        float4 bz = *(float4*)&Bs[k*196 +  64 + tx*4];
        float4 bg = *(float4*)&Bs[k*196 + 128 + tx*4];
        float av[4] = {a.x,a.y,a.z,a.w};
        #pragma unroll
        for(int r=0;r<4;r++){
            ar[r][0]+=av[r]*br.x; ar[r][1]+=av[r]*br.y; ar[r][2]+=av[r]*br.z; ar[r][3]+=av[r]*br.w;
            az[r][0]+=av[r]*bz.x; az[r][1]+=av[r]*bz.y; az[r][2]+=av[r]*bz.z; az[r][3]+=av[r]*bz.w;
            ag[r][0]+=av[r]*bg.x; ag[r][1]+=av[r]*bg.y; ag[r][2]+=av[r]*bg.z; ag[r][3]+=av[r]*bg.w;
        }
    }

    float4 b_ir = *(const float4*)&bih[      tx*4];
    float4 b_iz = *(const float4*)&bih[ 64 + tx*4];
    float4 b_ig = *(const float4*)&bih[128 + tx*4];
    float4 b_hr = *(const float4*)&bhh[      tx*4];
    float4 b_hz = *(const float4*)&bhh[ 64 + tx*4];
    float4 b_hg = *(const float4*)&bhh[128 + tx*4];
    float bir[4]={b_ir.x,b_ir.y,b_ir.z,b_ir.w}, biz[4]={b_iz.x,b_iz.y,b_iz.z,b_iz.w},
          big[4]={b_ig.x,b_ig.y,b_ig.z,b_ig.w}, bhr[4]={b_hr.x,b_hr.y,b_hr.z,b_hr.w},
          bhz[4]={b_hz.x,b_hz.y,b_hz.z,b_hz.w}, bhg[4]={b_hg.x,b_hg.y,b_hg.z,b_hg.w};

    #pragma unroll
    for(int r=0;r<4;r++){
        int n = m0 + ty*4 + r;
        if(n >= NN) continue;
        float4 gr = *(const float4*)&gi[(size_t)n*192 +       tx*4];
        float4 gz = *(const float4*)&gi[(size_t)n*192 +  64 + tx*4];
        float4 gg = *(const float4*)&gi[(size_t)n*192 + 128 + tx*4];
        float4 hv = *(const float4*)&hin[(size_t)n*64 + tx*4];
        float grv[4]={gr.x,gr.y,gr.z,gr.w}, gzv[4]={gz.x,gz.y,gz.z,gz.w},
              ggv[4]={gg.x,gg.y,gg.z,gg.w}, hvv[4]={hv.x,hv.y,hv.z,hv.w};
        float o[4];
        #pragma unroll
        for(int c=0;c<4;c++){
            float rr = sigm(grv[c] + bir[c] + ar[r][c] + bhr[c]);
            float zz = sigm(gzv[c] + biz[c] + az[r][c] + bhz[c]);
            float g  = tanhf(ggv[c] + big[c] + rr*(ag[r][c] + bhg[c]));
            o[c] = (1.f-zz)*g + zz*hvv[c];
        }
        *(float4*)&hout[(size_t)n*64 + tx*4] = make_float4(o[0],o[1],o[2],o[3]);
    }
}

// ---------------- edge-index output ----------------
__global__ void k_eout(const int* __restrict__ ei, float* __restrict__ out){
    int idx = blockIdx.x*blockDim.x+threadIdx.x;
    if(idx >= 2*EP) return;
    int row = idx/EP, e = idx - row*EP;
    int v = (e<EE) ? ei[row*EE + e] : (e-EE);
    out[idx] = (float)v;
}

// ---------------- host launcher ----------------
extern "C" void kernel_launch(void* const* d_in, const int* in_sizes, int n_in,
                              void* d_out, int out_size){
    const float* x    = (const float*)d_in[0];
    const int*   ei   = (const int*)  d_in[1];
    const float* W0   = (const float*)d_in[2];
    const float* as0  = (const float*)d_in[3];
    const float* ad0  = (const float*)d_in[4];
    const float* b0   = (const float*)d_in[5];
    const float* W1   = (const float*)d_in[6];
    const float* as1  = (const float*)d_in[7];
    const float* ad1  = (const float*)d_in[8];
    const float* b1   = (const float*)d_in[9];
    const float* lng  = (const float*)d_in[10];
    const float* lnb  = (const float*)d_in[11];
    const float* Wih  = (const float*)d_in[12];
    const float* Whh  = (const float*)d_in[13];
    const float* bih  = (const float*)d_in[14];
    const float* bhh  = (const float*)d_in[15];
    float* out = (float*)d_out;

    const int OFF_A  = NN*64;            // 640000
    const int OFF_EI = OFF_A + EP*4;     // 1320000

    float *pXW0,*pH0,*pXW1,*pHS,*pGI,*pHB0,*pHB1;
    __half *pXW0h,*pXW1h;
    float4 *pSS0,*pSD0,*pSS1,*pSD1;
    cudaGetSymbolAddress((void**)&pXW0, g_XW0);
    cudaGetSymbolAddress((void**)&pH0 , g_H0 );
    cudaGetSymbolAddress((void**)&pXW1, g_XW1);
    cudaGetSymbolAddress((void**)&pXW0h,g_XW0h);
    cudaGetSymbolAddress((void**)&pXW1h,g_XW1h);
    cudaGetSymbolAddress((void**)&pHS , g_HS );
    cudaGetSymbolAddress((void**)&pGI , g_GI );
    cudaGetSymbolAddress((void**)&pHB0, g_HB0);
    cudaGetSymbolAddress((void**)&pHB1, g_HB1);
    cudaGetSymbolAddress((void**)&pSS0, g_SSRC0);
    cudaGetSymbolAddress((void**)&pSD0, g_SDST0);
    cudaGetSymbolAddress((void**)&pSS1, g_SSRC1);
    cudaGetSymbolAddress((void**)&pSD1, g_SDST1);

    const int GRU_SMEM = (64*68 + 64*196) * 4;   // 67584
    cudaFuncSetAttribute(k_gru_fused, cudaFuncAttributeMaxDynamicSharedMemorySize, GRU_SMEM);

    const int WB = 7500;  // ROWS warps @ 8 warps/block

    // CSR build + init
    k_zero_cnt<<<(NN+255)/256,256>>>();
    k_zero_h0 <<<(NN*64+255)/256,256>>>();
    k_hist    <<<(EP+255)/256,256>>>(ei);
    k_scan    <<<1,1024>>>();
    k_scatter <<<(EP+255)/256,256>>>(ei);

    // layer 0 (A-load maps x [N,T,F] -> row-major [T*N,F] on the fly)
    gemm64<false,true ><<<dim3(938,1),256>>>(x,   W0, pXW0, pXW0h, ROWS, 64);
    k_svals<16,64><<<WB,256>>>(pXW0, as0, ad0, pSS0, pSD0);
    k_alpha<<<WB,256>>>(pSS0, pSD0, nullptr);
    k_agg0 <<<WB,256>>>(b0);

    // layer 1
    gemm64<false,false><<<dim3(938,4),256>>>(pH0, W1, pXW1, pXW1h, ROWS, 256);
    k_svals<64,256><<<WB,256>>>(pXW1, as1, ad1, pSS1, pSD1);
    k_alpha<<<WB,256>>>(pSS1, pSD1, out + OFF_A);
    k_agg1 <<<WB,256>>>(b1, lng, lnb);

    // GRU: batched input-projection GEMM, then fused per-step kernels
    gemm64<true,false><<<dim3(938,3),256>>>(pHS, Wih, pGI, ((__half*)0), ROWS, 192);
    for(int t=0; t<TT; t++){
        const float* hin = (t&1) ? pHB1 : pHB0;
        float* hout = (t==TT-1) ? out : ((t&1) ? pHB0 : pHB1);
        k_gru_fused<<<157,256,GRU_SMEM>>>(hin, pGI + (size_t)t*NN*192, Whh, bih, bhh, hout);
    }

    // edge index output
    k_eout<<<(2*EP+255)/256,256>>>(ei, out + OFF_EI);
    (void)in_sizes; (void)n_in; (void)out_size;
}

// round 5
// speedup vs baseline: 1.9002x; 1.1784x over previous
#include <cuda_runtime.h>
#include <cuda_fp16.h>
#include <math.h>

// ---------------- problem constants ----------------
#define NN   10000
#define TT   6
#define HIDD 64
#define EE   160000
#define EP   170000          // EE + NN self loops
#define ROWS (TT*NN)         // 60000

// ---------------- scratch (__device__ globals; no allocations) ----------------
__device__ float  g_XW0 [ROWS*64];
__device__ float  g_H0  [ROWS*64];
__device__ float  g_XW1 [ROWS*256];
__device__ __half g_XW0h[ROWS*64];
__device__ __half g_XW1h[ROWS*256];
__device__ float  g_HS  [ROWS*64];
__device__ float  g_GI  [ROWS*192];
__device__ float  g_HB0 [NN*64];
__device__ float  g_HB1 [NN*64];
__device__ float4 g_SSRC0[ROWS];
__device__ float4 g_SDST0[ROWS];
__device__ float4 g_SSRC1[ROWS];
__device__ float4 g_SDST1[ROWS];
__device__ float4 g_ALPHA[TT*EP];
__device__ int    g_CNT [NN];
__device__ int    g_ROWP[NN+1];
__device__ int    g_CUR [NN];
__device__ int    g_COL [EP];
__device__ int    g_EID [EP];

// ---------------- small helpers ----------------
__device__ __forceinline__ float lrelu(float x){ return x > 0.f ? x : 0.2f*x; }
__device__ __forceinline__ float eluf (float x){ return x > 0.f ? x : expm1f(x); }
__device__ __forceinline__ float sigm (float x){ return 1.f/(1.f+__expf(-x)); }
__device__ __forceinline__ float pick4(float4 a,int h){
    return h==0?a.x : (h==1?a.y : (h==2?a.z : a.w));
}

__device__ __forceinline__ void ldsm_x4(unsigned* r, const void* p){
    unsigned a = (unsigned)__cvta_generic_to_shared(p);
    asm volatile("ldmatrix.sync.aligned.m8n8.x4.shared.b16 {%0,%1,%2,%3}, [%4];"
        : "=r"(r[0]),"=r"(r[1]),"=r"(r[2]),"=r"(r[3]) : "r"(a));
}
__device__ __forceinline__ void ldsm_x4_t(unsigned* r, const void* p){
    unsigned a = (unsigned)__cvta_generic_to_shared(p);
    asm volatile("ldmatrix.sync.aligned.m8n8.x4.trans.shared.b16 {%0,%1,%2,%3}, [%4];"
        : "=r"(r[0]),"=r"(r[1]),"=r"(r[2]),"=r"(r[3]) : "r"(a));
}
__device__ __forceinline__ void mma16816(float* d, const unsigned* a, const unsigned* b){
    asm volatile("mma.sync.aligned.m16n8k16.row.col.f32.f16.f16.f32 "
        "{%0,%1,%2,%3}, {%4,%5,%6,%7}, {%8,%9}, {%0,%1,%2,%3};"
        : "+f"(d[0]),"+f"(d[1]),"+f"(d[2]),"+f"(d[3])
        : "r"(a[0]),"r"(a[1]),"r"(a[2]),"r"(a[3]), "r"(b[0]),"r"(b[1]));
}

// ---------------- CSR build ----------------
__global__ void k_zero_cnt(){ int i=blockIdx.x*blockDim.x+threadIdx.x; if(i<NN) g_CNT[i]=0; }
__global__ void k_zero_h0 (){ int i=blockIdx.x*blockDim.x+threadIdx.x; if(i<NN*64) g_HB0[i]=0.f; }

__global__ void k_hist(const int* __restrict__ ei){
    int e = blockIdx.x*blockDim.x+threadIdx.x;
    if(e>=EP) return;
    int d = (e<EE) ? ei[EE+e] : (e-EE);
    atomicAdd(&g_CNT[d],1);
}

// single-pass scan: 1024 threads x 10 elements each
__global__ void k_scan(){
    __shared__ int wsum[32];
    int tid = threadIdx.x, lane = tid&31, wid = tid>>5;
    int base = tid*10;
    int v[10]; int s=0;
    #pragma unroll
    for(int j=0;j<10;j++){
        int i = base+j;
        int x = (i<NN) ? g_CNT[i] : 0;
        v[j]=s; s+=x;
    }
    int x = s;
    #pragma unroll
    for(int off=1; off<32; off<<=1){
        int y = __shfl_up_sync(0xffffffffu, x, off);
        if(lane>=off) x += y;
    }
    if(lane==31) wsum[wid]=x;
    __syncthreads();
    if(wid==0){
        int w = wsum[lane];
        #pragma unroll
        for(int off=1; off<32; off<<=1){
            int y = __shfl_up_sync(0xffffffffu, w, off);
            if(lane>=off) w += y;
        }
        wsum[lane]=w;
    }
    __syncthreads();
    int excl = x - s + (wid ? wsum[wid-1] : 0);
    #pragma unroll
    for(int j=0;j<10;j++){
        int i = base+j;
        if(i<NN){ g_ROWP[i]=excl+v[j]; g_CUR[i]=excl+v[j]; }
    }
    if(tid==0) g_ROWP[NN]=wsum[31];
}

__global__ void k_scatter(const int* __restrict__ ei){
    int e = blockIdx.x*blockDim.x+threadIdx.x;
    if(e>=EP) return;
    int s,d;
    if(e<EE){ s=ei[e]; d=ei[EE+e]; } else { s=d=e-EE; }
    int p = atomicAdd(&g_CUR[d],1);
    g_COL[p]=s; g_EID[p]=e;
}

// ---------------- HMMA GEMM: C[M,Nc] = A[M,64] @ B(64,Nc), fp16 in / fp32 acc ----------------
// TRANSB: B given as [Nc,64] row-major (use B^T)
// XMAP:   A row i maps to x[((i%NN)*TT + i/NN)*64]
// Ch:     optional fp16 copy of C
#define LDH 72   // 64 + 8 halfs pad (row stride 144B)
template<bool TRANSB, bool XMAP>
__global__ void hgemm64(const float* __restrict__ A, const float* __restrict__ B,
                        float* __restrict__ C, __half* __restrict__ Ch, int M, int Nc){
    __shared__ __align__(16) __half As[64*LDH];
    __shared__ __align__(16) __half Bs[64*LDH];
    int m0 = blockIdx.x*64, n0 = blockIdx.y*64;
    int tid = threadIdx.x;

    // load A (fp32 -> fp16)
    #pragma unroll
    for(int j=0;j<4;j++){
        int idx = tid + j*256;
        int r = idx>>4, kq = (idx&15)*4;
        float4 v = make_float4(0.f,0.f,0.f,0.f);
        int i = m0+r;
        if(i < M){
            size_t off;
            if(XMAP){ int t=i/NN, n=i-t*NN; off=((size_t)n*TT+t)*64 + kq; }
            else     { off=(size_t)i*64 + kq; }
            v = *(const float4*)&A[off];
        }
        __half2* p = (__half2*)&As[r*LDH + kq];
        p[0] = __floats2half2_rn(v.x,v.y);
        p[1] = __floats2half2_rn(v.z,v.w);
    }
    // load B
    if(!TRANSB){
        #pragma unroll
        for(int j=0;j<4;j++){
            int idx = tid + j*256;
            int k = idx>>4, nq=(idx&15)*4;
            float4 v = *(const float4*)&B[(size_t)k*Nc + n0 + nq];
            __half2* p = (__half2*)&Bs[k*LDH + nq];
            p[0] = __floats2half2_rn(v.x,v.y);
            p[1] = __floats2half2_rn(v.z,v.w);
        }
    } else {
        #pragma unroll
        for(int j=0;j<4;j++){
            int idx = tid + j*256;
            int n = idx>>4, kq=(idx&15)*4;
            float4 v = *(const float4*)&B[(size_t)(n0+n)*64 + kq];
            Bs[(kq+0)*LDH+n]=__float2half_rn(v.x);
            Bs[(kq+1)*LDH+n]=__float2half_rn(v.y);
            Bs[(kq+2)*LDH+n]=__float2half_rn(v.z);
            Bs[(kq+3)*LDH+n]=__float2half_rn(v.w);
        }
    }
    __syncthreads();

    int wid = tid>>5, lane = tid&31;
    int wm = wid&3, wn = wid>>2;        // 4 m-tiles x 2 n-tiles
    int m_base = wm*16, n_base = wn*32;

    float acc[4][4];
    #pragma unroll
    for(int nb=0;nb<4;nb++)
        #pragma unroll
        for(int c=0;c<4;c++) acc[nb][c]=0.f;

    int lr = lane&15, lc = lane>>4;     // ldmatrix addressing
    #pragma unroll
    for(int kc=0; kc<4; kc++){
        unsigned a[4];
        ldsm_x4(a, &As[(m_base+lr)*LDH + kc*16 + lc*8]);
        unsigned b01[4], b23[4];
        ldsm_x4_t(b01, &Bs[(kc*16+lr)*LDH + n_base      + lc*8]);
        ldsm_x4_t(b23, &Bs[(kc*16+lr)*LDH + n_base + 16 + lc*8]);
        mma16816(acc[0], a, b01);
        mma16816(acc[1], a, b01+2);
        mma16816(acc[2], a, b23);
        mma16816(acc[3], a, b23+2);
    }

    // epilogue: write C fp32 (+ optional fp16 copy)
    int grp = lane>>2, tg = lane&3;
    #pragma unroll
    for(int nb=0;nb<4;nb++){
        int col = n0 + n_base + nb*8 + tg*2;
        int m_a = m0 + m_base + grp;
        int m_b = m_a + 8;
        if(m_a < M){
            size_t o = (size_t)m_a*Nc + col;
            *(float2*)&C[o] = make_float2(acc[nb][0],acc[nb][1]);
            if(Ch) *(__half2*)&Ch[o] = __floats2half2_rn(acc[nb][0],acc[nb][1]);
        }
        if(m_b < M){
            size_t o = (size_t)m_b*Nc + col;
            *(float2*)&C[o] = make_float2(acc[nb][2],acc[nb][3]);
            if(Ch) *(__half2*)&Ch[o] = __floats2half2_rn(acc[nb][2],acc[nb][3]);
        }
    }
}

// ---------------- per-row attention scalars ----------------
template<int C,int HC>
__global__ void k_svals(const float* __restrict__ XW,
                        const float* __restrict__ asrc, const float* __restrict__ adst,
                        float4* __restrict__ SS, float4* __restrict__ SD){
    int w = (blockIdx.x*blockDim.x+threadIdx.x)>>5;
    if(w>=ROWS) return;
    int lane = threadIdx.x&31;
    float s0=0,s1=0,s2=0,s3=0,d0=0,d1=0,d2=0,d3=0;
    const float* row = XW + (size_t)w*HC;
    #pragma unroll
    for(int it=0; it<HC/32; it++){
        int idx = lane + it*32;
        float v  = row[idx];
        float as = asrc[idx], ad = adst[idx];
        int h = idx / C;
        if(h==0){ s0+=v*as; d0+=v*ad; }
        else if(h==1){ s1+=v*as; d1+=v*ad; }
        else if(h==2){ s2+=v*as; d2+=v*ad; }
        else { s3+=v*as; d3+=v*ad; }
    }
    #pragma unroll
    for(int off=16; off; off>>=1){
        s0+=__shfl_xor_sync(0xffffffffu,s0,off); s1+=__shfl_xor_sync(0xffffffffu,s1,off);
        s2+=__shfl_xor_sync(0xffffffffu,s2,off); s3+=__shfl_xor_sync(0xffffffffu,s3,off);
        d0+=__shfl_xor_sync(0xffffffffu,d0,off); d1+=__shfl_xor_sync(0xffffffffu,d1,off);
        d2+=__shfl_xor_sync(0xffffffffu,d2,off); d3+=__shfl_xor_sync(0xffffffffu,d3,off);
    }
    if(lane==0){ SS[w]=make_float4(s0,s1,s2,s3); SD[w]=make_float4(d0,d1,d2,d3); }
}

// ---------------- segment softmax (alpha), warp per (t,node) ----------------
__global__ void k_alpha(const float4* __restrict__ SS, const float4* __restrict__ SD,
                        float* __restrict__ out_alpha){
    int w = (blockIdx.x*blockDim.x+threadIdx.x)>>5;
    if(w>=ROWS) return;
    int lane = threadIdx.x&31;
    int t = w/NN, n = w - t*NN;
    int beg = g_ROWP[n], end = g_ROWP[n+1];
    float4 sd = SD[w];
    const float4* ss = SS + (size_t)t*NN;

    float m0=-1e30f,m1=-1e30f,m2=-1e30f,m3=-1e30f;
    for(int b=beg; b<end; b+=32){
        int e=b+lane;
        if(e<end){
            float4 s = ss[g_COL[e]];
            m0=fmaxf(m0,lrelu(s.x+sd.x)); m1=fmaxf(m1,lrelu(s.y+sd.y));
            m2=fmaxf(m2,lrelu(s.z+sd.z)); m3=fmaxf(m3,lrelu(s.w+sd.w));
        }
    }
    #pragma unroll
    for(int off=16; off; off>>=1){
        m0=fmaxf(m0,__shfl_xor_sync(0xffffffffu,m0,off));
        m1=fmaxf(m1,__shfl_xor_sync(0xffffffffu,m1,off));
        m2=fmaxf(m2,__shfl_xor_sync(0xffffffffu,m2,off));
        m3=fmaxf(m3,__shfl_xor_sync(0xffffffffu,m3,off));
    }
    float q0=0,q1=0,q2=0,q3=0;
    for(int b=beg; b<end; b+=32){
        int e=b+lane;
        if(e<end){
            float4 s = ss[g_COL[e]];
            q0+=__expf(lrelu(s.x+sd.x)-m0); q1+=__expf(lrelu(s.y+sd.y)-m1);
            q2+=__expf(lrelu(s.z+sd.z)-m2); q3+=__expf(lrelu(s.w+sd.w)-m3);
        }
    }
    #pragma unroll
    for(int off=16; off; off>>=1){
        q0+=__shfl_xor_sync(0xffffffffu,q0,off); q1+=__shfl_xor_sync(0xffffffffu,q1,off);
        q2+=__shfl_xor_sync(0xffffffffu,q2,off); q3+=__shfl_xor_sync(0xffffffffu,q3,off);
    }
    float i0=1.f/(q0+1e-16f), i1=1.f/(q1+1e-16f), i2=1.f/(q2+1e-16f), i3=1.f/(q3+1e-16f);
    bool wo = (out_alpha != nullptr) && (t == TT-1);
    for(int b=beg; b<end; b+=32){
        int e=b+lane;
        if(e<end){
            float4 s = ss[g_COL[e]];
            float4 a;
            a.x = __expf(lrelu(s.x+sd.x)-m0)*i0;
            a.y = __expf(lrelu(s.y+sd.y)-m1)*i1;
            a.z = __expf(lrelu(s.z+sd.z)-m2)*i2;
            a.w = __expf(lrelu(s.w+sd.w)-m3)*i3;
            g_ALPHA[(size_t)t*EP + e] = a;
            if(wo) ((float4*)out_alpha)[g_EID[e]] = a;
        }
    }
}

// ---------------- layer-0 aggregate (+b0, ELU) -> H0 (fp16 gather) ----------------
__global__ void k_agg0(const float* __restrict__ b0v){
    int w = (blockIdx.x*blockDim.x+threadIdx.x)>>5;
    if(w>=ROWS) return;
    int lane = threadIdx.x&31;
    int t = w/NN, n = w - t*NN;
    int beg = g_ROWP[n], end = g_ROWP[n+1];
    int c0 = 2*lane, h = lane>>3;
    const __half*  xw = g_XW0h + (size_t)t*NN*64;
    const float4*  al = g_ALPHA + (size_t)t*EP;
    float ax=0.f, ay=0.f;
    for(int e=beg; e<end; e++){
        float4 a = al[e];
        float ah = pick4(a,h);
        int cs = g_COL[e];
        float2 v = __half22float2(*(const __half2*)&xw[(size_t)cs*64 + c0]);
        ax += ah*v.x; ay += ah*v.y;
    }
    ax = eluf(ax + b0v[c0]); ay = eluf(ay + b0v[c0+1]);
    *(float2*)&g_H0[(size_t)w*64 + c0] = make_float2(ax,ay);
}

// ---------------- layer-1 aggregate (mean heads, +b1, ELU, LayerNorm) -> HS ----------------
__global__ void k_agg1(const float* __restrict__ b1v,
                       const float* __restrict__ lng, const float* __restrict__ lnb){
    int w = (blockIdx.x*blockDim.x+threadIdx.x)>>5;
    if(w>=ROWS) return;
    int lane = threadIdx.x&31;
    int t = w/NN, n = w - t*NN;
    int beg = g_ROWP[n], end = g_ROWP[n+1];
    int c0 = 2*lane;
    const __half*  xw = g_XW1h + (size_t)t*NN*256;
    const float4*  al = g_ALPHA + (size_t)t*EP;
    float a0x=0,a0y=0,a1x=0,a1y=0,a2x=0,a2y=0,a3x=0,a3y=0;
    for(int e=beg; e<end; e++){
        float4 a = al[e];
        int cs = g_COL[e];
        const __half* r = xw + (size_t)cs*256;
        float2 v0 = __half22float2(*(const __half2*)&r[      c0]);
        float2 v1 = __half22float2(*(const __half2*)&r[ 64 + c0]);
        float2 v2 = __half22float2(*(const __half2*)&r[128 + c0]);
        float2 v3 = __half22float2(*(const __half2*)&r[192 + c0]);
        a0x += a.x*v0.x; a0y += a.x*v0.y;
        a1x += a.y*v1.x; a1y += a.y*v1.y;
        a2x += a.z*v2.x; a2y += a.z*v2.y;
        a3x += a.w*v3.x; a3y += a.w*v3.y;
    }
    float vx = (a0x+a1x+a2x+a3x)*0.25f + b1v[c0];
    float vy = (a0y+a1y+a2y+a3y)*0.25f + b1v[c0+1];
    vx = eluf(vx); vy = eluf(vy);
    float s  = vx+vy;
    float s2 = vx*vx + vy*vy;
    #pragma unroll
    for(int off=16; off; off>>=1){
        s  += __shfl_xor_sync(0xffffffffu,s ,off);
        s2 += __shfl_xor_sync(0xffffffffu,s2,off);
    }
    float mu   = s*(1.f/64.f);
    float var  = fmaxf(s2*(1.f/64.f) - mu*mu, 0.f);
    float rstd = rsqrtf(var + 1e-5f);
    float ox = (vx-mu)*rstd*lng[c0]   + lnb[c0];
    float oy = (vy-mu)*rstd*lng[c0+1] + lnb[c0+1];
    *(float2*)&g_HS[(size_t)w*64 + c0] = make_float2(ox,oy);
}

// ---------------- fused GRU step: gh GEMM + gates ----------------
__global__ void k_gru_fused(const float* __restrict__ hin, const float* __restrict__ gi,
                            const float* __restrict__ Whh,
                            const float* __restrict__ bih, const float* __restrict__ bhh,
                            float* __restrict__ hout){
    extern __shared__ float sm[];
    float* As = sm;                 // [64k][68]
    float* Bs = sm + 64*68;         // [64k][196]
    int m0 = blockIdx.x*64, tid = threadIdx.x;

    #pragma unroll
    for(int j=0;j<4;j++){
        int idx = tid + j*256;
        int r = idx>>4, kq=(idx&15)*4;
        float4 v = make_float4(0.f,0.f,0.f,0.f);
        if(m0+r < NN) v = *(const float4*)&hin[(size_t)(m0+r)*64 + kq];
        As[(kq+0)*68+r]=v.x; As[(kq+1)*68+r]=v.y;
        As[(kq+2)*68+r]=v.z; As[(kq+3)*68+r]=v.w;
    }
    #pragma unroll
    for(int j=0;j<12;j++){
        int idx = tid + j*256;
        int row = idx>>4, kq=(idx&15)*4;
        float4 v = *(const float4*)&Whh[(size_t)row*64 + kq];
        Bs[(kq+0)*196+row]=v.x; Bs[(kq+1)*196+row]=v.y;
        Bs[(kq+2)*196+row]=v.z; Bs[(kq+3)*196+row]=v.w;
    }
    __syncthreads();

    int ty = tid>>4, tx = tid&15;
    float ar[4][4], az[4][4], ag[4][4];
    #pragma unroll
    for(int r=0;r<4;r++)
        #pragma unroll
        for(int c=0;c<4;c++){ ar[r][c]=0.f; az[r][c]=0.f; ag[r][c]=0.f; }

    #pragma unroll
    for(int k=0;k<64;k++){
        float4 a  = *(float4*)&As[k*68 + ty*4];
        float4 br = *(float4*)&Bs[k*196 +       tx*4];
        float4 bz = *(float4*)&Bs[k*196 +  64 + tx*4];
        float4 bg = *(float4*)&Bs[k*196 + 128 + tx*4];
        float av[4] = {a.x,a.y,a.z,a.w};
        #pragma unroll
        for(int r=0;r<4;r++){
            ar[r][0]+=av[r]*br.x; ar[r][1]+=av[r]*br.y; ar[r][2]+=av[r]*br.z; ar[r][3]+=av[r]*br.w;
            az[r][0]+=av[r]*bz.x; az[r][1]+=av[r]*bz.y; az[r][2]+=av[r]*bz.z; az[r][3]+=av[r]*bz.w;
            ag[r][0]+=av[r]*bg.x; ag[r][1]+=av[r]*bg.y; ag[r][2]+=av[r]*bg.z; ag[r][3]+=av[r]*bg.w;
        }
    }

    float4 b_ir = *(const float4*)&bih[      tx*4];
    float4 b_iz = *(const float4*)&bih[ 64 + tx*4];
    float4 b_ig = *(const float4*)&bih[128 + tx*4];
    float4 b_hr = *(const float4*)&bhh[      tx*4];
    float4 b_hz = *(const float4*)&bhh[ 64 + tx*4];
    float4 b_hg = *(const float4*)&bhh[128 + tx*4];
    float bir[4]={b_ir.x,b_ir.y,b_ir.z,b_ir.w}, biz[4]={b_iz.x,b_iz.y,b_iz.z,b_iz.w},
          big[4]={b_ig.x,b_ig.y,b_ig.z,b_ig.w}, bhr[4]={b_hr.x,b_hr.y,b_hr.z,b_hr.w},
          bhz[4]={b_hz.x,b_hz.y,b_hz.z,b_hz.w}, bhg[4]={b_hg.x,b_hg.y,b_hg.z,b_hg.w};

    #pragma unroll
    for(int r=0;r<4;r++){
        int n = m0 + ty*4 + r;
        if(n >= NN) continue;
        float4 gr = *(const float4*)&gi[(size_t)n*192 +       tx*4];
        float4 gz = *(const float4*)&gi[(size_t)n*192 +  64 + tx*4];
        float4 gg = *(const float4*)&gi[(size_t)n*192 + 128 + tx*4];
        float4 hv = *(const float4*)&hin[(size_t)n*64 + tx*4];
        float grv[4]={gr.x,gr.y,gr.z,gr.w}, gzv[4]={gz.x,gz.y,gz.z,gz.w},
              ggv[4]={gg.x,gg.y,gg.z,gg.w}, hvv[4]={hv.x,hv.y,hv.z,hv.w};
        float o[4];
        #pragma unroll
        for(int c=0;c<4;c++){
            float rr = sigm(grv[c] + bir[c] + ar[r][c] + bhr[c]);
            float zz = sigm(gzv[c] + biz[c] + az[r][c] + bhz[c]);
            float g  = tanhf(ggv[c] + big[c] + rr*(ag[r][c] + bhg[c]));
            o[c] = (1.f-zz)*g + zz*hvv[c];
        }
        *(float4*)&hout[(size_t)n*64 + tx*4] = make_float4(o[0],o[1],o[2],o[3]);
    }
}

// ---------------- edge-index output ----------------
__global__ void k_eout(const int* __restrict__ ei, float* __restrict__ out){
    int idx = blockIdx.x*blockDim.x+threadIdx.x;
    if(idx >= 2*EP) return;
    int row = idx/EP, e = idx - row*EP;
    int v = (e<EE) ? ei[row*EE + e] : (e-EE);
    out[idx] = (float)v;
}

// ---------------- host launcher ----------------
extern "C" void kernel_launch(void* const* d_in, const int* in_sizes, int n_in,
                              void* d_out, int out_size){
    const float* x    = (const float*)d_in[0];
    const int*   ei   = (const int*)  d_in[1];
    const float* W0   = (const float*)d_in[2];
    const float* as0  = (const float*)d_in[3];
    const float* ad0  = (const float*)d_in[4];
    const float* b0   = (const float*)d_in[5];
    const float* W1   = (const float*)d_in[6];
    const float* as1  = (const float*)d_in[7];
    const float* ad1  = (const float*)d_in[8];
    const float* b1   = (const float*)d_in[9];
    const float* lng  = (const float*)d_in[10];
    const float* lnb  = (const float*)d_in[11];
    const float* Wih  = (const float*)d_in[12];
    const float* Whh  = (const float*)d_in[13];
    const float* bih  = (const float*)d_in[14];
    const float* bhh  = (const float*)d_in[15];
    float* out = (float*)d_out;

    const int OFF_A  = NN*64;            // 640000
    const int OFF_EI = OFF_A + EP*4;     // 1320000

    float *pXW0,*pH0,*pXW1,*pHS,*pGI,*pHB0,*pHB1;
    __half *pXW0h,*pXW1h;
    float4 *pSS0,*pSD0,*pSS1,*pSD1;
    cudaGetSymbolAddress((void**)&pXW0, g_XW0);
    cudaGetSymbolAddress((void**)&pH0 , g_H0 );
    cudaGetSymbolAddress((void**)&pXW1, g_XW1);
    cudaGetSymbolAddress((void**)&pXW0h,g_XW0h);
    cudaGetSymbolAddress((void**)&pXW1h,g_XW1h);
    cudaGetSymbolAddress((void**)&pHS , g_HS );
    cudaGetSymbolAddress((void**)&pGI , g_GI );
    cudaGetSymbolAddress((void**)&pHB0, g_HB0);
    cudaGetSymbolAddress((void**)&pHB1, g_HB1);
    cudaGetSymbolAddress((void**)&pSS0, g_SSRC0);
    cudaGetSymbolAddress((void**)&pSD0, g_SDST0);
    cudaGetSymbolAddress((void**)&pSS1, g_SSRC1);
    cudaGetSymbolAddress((void**)&pSD1, g_SDST1);

    const int GRU_SMEM = (64*68 + 64*196) * 4;
    cudaFuncSetAttribute(k_gru_fused, cudaFuncAttributeMaxDynamicSharedMemorySize, GRU_SMEM);

    const int WB = 7500;

    // CSR build + init
    k_zero_cnt<<<(NN+255)/256,256>>>();
    k_zero_h0 <<<(NN*64+255)/256,256>>>();
    k_hist    <<<(EP+255)/256,256>>>(ei);
    k_scan    <<<1,1024>>>();
    k_scatter <<<(EP+255)/256,256>>>(ei);

    // layer 0
    hgemm64<false,true ><<<dim3(938,1),256>>>(x,   W0, pXW0, pXW0h, ROWS, 64);
    k_svals<16,64><<<WB,256>>>(pXW0, as0, ad0, pSS0, pSD0);
    k_alpha<<<WB,256>>>(pSS0, pSD0, nullptr);
    k_agg0 <<<WB,256>>>(b0);

    // layer 1
    hgemm64<false,false><<<dim3(938,4),256>>>(pH0, W1, pXW1, pXW1h, ROWS, 256);
    k_svals<64,256><<<WB,256>>>(pXW1, as1, ad1, pSS1, pSD1);
    k_alpha<<<WB,256>>>(pSS1, pSD1, out + OFF_A);
    k_agg1 <<<WB,256>>>(b1, lng, lnb);

    // GRU
    hgemm64<true,false><<<dim3(938,3),256>>>(pHS, Wih, pGI, ((__half*)0), ROWS, 192);
    for(int t=0; t<TT; t++){
        const float* hin = (t&1) ? pHB1 : pHB0;
        float* hout = (t==TT-1) ? out : ((t&1) ? pHB0 : pHB1);
        k_gru_fused<<<157,256,GRU_SMEM>>>(hin, pGI + (size_t)t*NN*192, Whh, bih, bhh, hout);
    }

    // edge index output
    k_eout<<<(2*EP+255)/256,256>>>(ei, out + OFF_EI);
    (void)in_sizes; (void)n_in; (void)out_size;
}